// round 1
// baseline (speedup 1.0000x reference)
#include <cuda_runtime.h>

// ---------------- problem constants (fixed shapes) ----------------
#define Bc 2
#define Nc 50000
#define Cc 15
#define PAIRS (Bc*Cc)          // 30
#define CS 4                   // cluster size (CTAs per (b,c) pair)
#define NPER (Nc/CS)           // 12500 candidates per CTA
#define TH 512
#define CPT ((NPER + TH - 1)/TH) // 25 candidates per thread
#define MAXDET 300
#define NEGV (-1e9f)

// scratch (no allocations allowed -> __device__ globals)
__device__ int   g_pick_idx[PAIRS*MAXDET];
__device__ float g_pick_score[PAIRS*MAXDET];

// pack (score, index) into a u64 so that max() == (higher score, then LOWER index)
__device__ __forceinline__ unsigned long long packkey(float s, unsigned int gidx){
    unsigned int sb = __float_as_uint(s);
    sb = (sb & 0x80000000u) ? ~sb : (sb | 0x80000000u);   // monotone float->uint
    return ((unsigned long long)sb << 32) | (unsigned int)(~gidx);
}

__device__ __forceinline__ unsigned long long warp_max_u64(unsigned long long k){
    #pragma unroll
    for (int o = 16; o; o >>= 1){
        unsigned long long other = __shfl_xor_sync(0xFFFFFFFFu, k, o);
        if (other > k) k = other;
    }
    return k;
}

extern __shared__ float4 s_boxes[];   // NPER float4 boxes (200 KB)

__global__ void __cluster_dims__(CS,1,1) __launch_bounds__(TH,1)
nms_kernel(const float* __restrict__ boxes, const float* __restrict__ cls)
{
    __shared__ unsigned long long s_warp[TH/32];
    __shared__ unsigned long long s_slots[2][CS];   // double-buffered cluster exchange

    const int pair = blockIdx.x >> 2;     // which (b,c)
    const int rank = blockIdx.x & 3;      // cluster rank
    const int b = pair / Cc;
    const int c = pair % Cc;
    const int base = rank * NPER;         // candidate offset within image
    const int t = threadIdx.x;

    const float4* gbox = reinterpret_cast<const float4*>(boxes) + (size_t)b * Nc;

    // ---- load this CTA's boxes into SMEM (coalesced) ----
    for (int i = t; i < NPER; i += TH) s_boxes[i] = gbox[base + i];

    // ---- load + threshold scores into registers ----
    float sc[CPT], ar[CPT];
    #pragma unroll
    for (int k = 0; k < CPT; k++){
        int li = k*TH + t;
        float s = NEGV;
        if (li < NPER){
            float v = cls[((size_t)(b*Nc + base + li))*Cc + c];
            if (v > 0.05f) s = v;
        }
        sc[k] = s;
    }
    __syncthreads();
    #pragma unroll
    for (int k = 0; k < CPT; k++){
        int li = k*TH + t;
        float a = 0.f;
        if (li < NPER){ float4 bx = s_boxes[li]; a = (bx.z - bx.x) * (bx.w - bx.y); }
        ar[k] = a;
    }

    // ---- initial local argmax ----
    unsigned long long key = 0ull;
    #pragma unroll
    for (int k = 0; k < CPT; k++){
        unsigned long long kk = packkey(sc[k], (unsigned)(base + k*TH + t));
        if (kk > key) key = kk;
    }

    // ---- 300 sequential NMS iterations ----
    for (int iter = 0; iter < MAXDET; iter++){
        // CTA reduce
        key = warp_max_u64(key);
        if ((t & 31) == 0) s_warp[t >> 5] = key;
        __syncthreads();
        if (t < 32){
            unsigned long long k2 = (t < TH/32) ? s_warp[t] : 0ull;
            k2 = warp_max_u64(k2);
            if (t == 0){
                // broadcast this CTA's partial to slot[parity][rank] of all 4 CTAs
                unsigned int laddr = (unsigned int)__cvta_generic_to_shared(&s_slots[iter & 1][rank]);
                #pragma unroll
                for (int r = 0; r < CS; r++){
                    unsigned int raddr;
                    asm volatile("mapa.shared::cluster.u32 %0, %1, %2;" : "=r"(raddr) : "r"(laddr), "r"(r));
                    asm volatile("st.shared::cluster.u64 [%0], %1;" :: "r"(raddr), "l"(k2) : "memory");
                }
            }
        }
        // cluster barrier: arrive has release semantics (orders the remote stores)
        asm volatile("barrier.cluster.arrive.aligned;" ::: "memory");
        asm volatile("barrier.cluster.wait.aligned;"   ::: "memory");

        // everyone computes the cluster-wide winner (identical across CTAs)
        unsigned long long w = s_slots[iter & 1][0];
        #pragma unroll
        for (int r = 1; r < CS; r++){
            unsigned long long v = s_slots[iter & 1][r];
            if (v > w) w = v;
        }
        const unsigned int widx = ~((unsigned int)w);          // image-global candidate idx
        const unsigned int sb = (unsigned int)(w >> 32);
        const float ws = (sb & 0x80000000u) ? __uint_as_float(sb ^ 0x80000000u)
                                            : __uint_as_float(~sb);

        if (rank == 0 && t == 0){
            g_pick_idx  [pair*MAXDET + iter] = (int)widx;
            g_pick_score[pair*MAXDET + iter] = ws;
        }

        // pivot box (uniform 16B load, L2-resident)
        const float4 pb = gbox[widx];
        const float  pa = (pb.z - pb.x) * (pb.w - pb.y);

        // fused suppress + next argmax
        key = 0ull;
        #pragma unroll
        for (int k = 0; k < CPT; k++){
            int li = k*TH + t;
            unsigned int gi = (unsigned)(base + li);
            float s = sc[k];
            if (s != NEGV){
                if (gi == widx){
                    s = NEGV;
                } else {
                    float4 bx = s_boxes[li];
                    float y1 = fmaxf(pb.x, bx.x);
                    float x1 = fmaxf(pb.y, bx.y);
                    float y2 = fminf(pb.z, bx.z);
                    float x2 = fminf(pb.w, bx.w);
                    float inter = fmaxf(y2 - y1, 0.f) * fmaxf(x2 - x1, 0.f);
                    float denom = pa + ar[k] - inter + 1e-9f;
                    if (__fdiv_rn(inter, denom) > 0.5f) s = NEGV;   // IEEE div to match XLA
                }
                sc[k] = s;
            }
            unsigned long long kk = packkey(s, gi);
            if (kk > key) key = kk;
        }
    }

    // trailing sync so no CTA exits while peers may still address its SMEM
    asm volatile("barrier.cluster.arrive.aligned;" ::: "memory");
    asm volatile("barrier.cluster.wait.aligned;"   ::: "memory");
}

// ---------------- per-image top-300 via 15-way sorted merge ----------------
__global__ void __launch_bounds__(256)
finalize_kernel(const float* __restrict__ boxes, float* __restrict__ out)
{
    const int b = blockIdx.x;
    const int t = threadIdx.x;

    __shared__ float s_sc[Cc*MAXDET];
    __shared__ int   s_idx[Cc*MAXDET];
    __shared__ int   s_selflat[MAXDET];

    for (int i = t; i < Cc*MAXDET; i += blockDim.x){
        s_sc[i]  = g_pick_score[b*Cc*MAXDET + i];
        s_idx[i] = g_pick_idx  [b*Cc*MAXDET + i];
    }
    __syncthreads();

    if (t < 32){
        int head = 0;
        const int c = t;
        const bool act = (c < Cc);
        for (int j = 0; j < MAXDET; j++){
            unsigned long long k = 0ull;
            if (act && head < MAXDET){
                int flat = c*MAXDET + head;
                k = packkey(s_sc[flat], (unsigned)flat);
            }
            k = warp_max_u64(k);
            unsigned int flat = ~((unsigned int)k);
            if (t == 0) s_selflat[j] = (int)flat;
            if (act && (int)(flat / MAXDET) == c) head++;   // winner lane advances
        }
    }
    __syncthreads();

    const float4* gbox = reinterpret_cast<const float4*>(boxes) + (size_t)b * Nc;
    float4* obox   = reinterpret_cast<float4*>(out);
    float*  oscore = out + (size_t)Bc*MAXDET*4;
    float*  olab   = out + (size_t)Bc*MAXDET*5;

    for (int j = t; j < MAXDET; j += blockDim.x){
        int flat = s_selflat[j];
        float s = s_sc[flat];
        bool valid = s > (NEGV * 0.5f);    // matches top_s > NEG/2
        float4 bx;
        if (valid) bx = gbox[s_idx[flat]];
        else       bx = make_float4(-1.f, -1.f, -1.f, -1.f);
        obox  [b*MAXDET + j] = bx;
        oscore[b*MAXDET + j] = valid ? s : -1.f;
        olab  [b*MAXDET + j] = valid ? (float)(flat / MAXDET) : -1.f;
    }
}

extern "C" void kernel_launch(void* const* d_in, const int* in_sizes, int n_in,
                              void* d_out, int out_size)
{
    const float* boxes = (const float*)d_in[0];
    const float* cls   = (const float*)d_in[1];
    // defensive: if input order is swapped, fix it by element count
    if (n_in >= 2 && in_sizes[0] == Bc*Nc*Cc && in_sizes[1] == Bc*Nc*4){
        const float* tmp = boxes; boxes = cls; cls = tmp;
    }

    cudaFuncSetAttribute(nms_kernel, cudaFuncAttributeMaxDynamicSharedMemorySize,
                         NPER * (int)sizeof(float4));

    nms_kernel<<<PAIRS*CS, TH, NPER*(int)sizeof(float4)>>>(boxes, cls);
    finalize_kernel<<<Bc, 256>>>(boxes, (float*)d_out);
}

// round 2
// speedup vs baseline: 1.5747x; 1.5747x over previous
#include <cuda_runtime.h>

// ---------------- problem constants (fixed shapes) ----------------
#define Bc 2
#define Nc 50000
#define Cc 15
#define PAIRS (Bc*Cc)          // 30
#define CS 4                   // cluster size (CTAs per (b,c) pair)
#define NPER (Nc/CS)           // 12500 candidates per CTA
#define TH 512
#define CPT ((NPER + TH - 1)/TH) // 25 candidates per thread
#define MAXDET 300
#define NEGV (-1e9f)
#define NK (Cc*MAXDET)         // 4500
#define P2 8192                // bitonic size

// scratch (no allocations allowed -> __device__ globals)
__device__ int   g_pick_idx[PAIRS*MAXDET];
__device__ float g_pick_score[PAIRS*MAXDET];

// pack (score, index) into a u64 so that max() == (higher score, then LOWER index)
__device__ __forceinline__ unsigned long long packkey(float s, unsigned int gidx){
    unsigned int sb = __float_as_uint(s);
    sb = (sb & 0x80000000u) ? ~sb : (sb | 0x80000000u);   // monotone float->uint
    return ((unsigned long long)sb << 32) | (unsigned int)(~gidx);
}
__device__ __forceinline__ float unpackscore(unsigned long long k){
    unsigned int sb = (unsigned int)(k >> 32);
    return (sb & 0x80000000u) ? __uint_as_float(sb ^ 0x80000000u)
                              : __uint_as_float(~sb);
}
__device__ __forceinline__ unsigned long long warp_max_u64(unsigned long long k){
    #pragma unroll
    for (int o = 16; o; o >>= 1){
        unsigned long long other = __shfl_xor_sync(0xFFFFFFFFu, k, o);
        if (other > k) k = other;
    }
    return k;
}

extern __shared__ float4 s_boxes[];   // CPT*TH float4 (204800 B; >= NPER, OOB lanes masked)

__global__ void __cluster_dims__(CS,1,1) __launch_bounds__(TH,1)
nms_kernel(const float* __restrict__ boxes, const float* __restrict__ cls)
{
    __shared__ unsigned long long s_warp[32];
    __shared__ unsigned long long s_key [2][CS];    // double-buffered cluster exchange
    __shared__ __align__(16) float4 s_pbox[2][CS];
    __shared__ unsigned long long s_mbar[2];

    const int pair = blockIdx.x >> 2;     // which (b,c)
    const int rank = blockIdx.x & 3;      // cluster rank
    const int b = pair / Cc;
    const int c = pair % Cc;
    const int base = rank * NPER;         // candidate offset within image
    const int t = threadIdx.x;

    const float4* gbox = reinterpret_cast<const float4*>(boxes) + (size_t)b * Nc;

    if (t < 32) s_warp[t] = 0ull;
    if (t == 0){
        unsigned int m0 = (unsigned int)__cvta_generic_to_shared(&s_mbar[0]);
        unsigned int m1 = (unsigned int)__cvta_generic_to_shared(&s_mbar[1]);
        asm volatile("mbarrier.init.shared.b64 [%0], %1;" :: "r"(m0), "r"(CS) : "memory");
        asm volatile("mbarrier.init.shared.b64 [%0], %1;" :: "r"(m1), "r"(CS) : "memory");
    }

    // ---- load this CTA's boxes into SMEM (coalesced) ----
    for (int i = t; i < NPER; i += TH) s_boxes[i] = gbox[base + i];

    // ---- load + threshold scores into registers ----
    float sc[CPT], ar[CPT];
    #pragma unroll
    for (int k = 0; k < CPT; k++){
        int li = k*TH + t;
        float s = NEGV;
        if (li < NPER){
            float v = cls[((size_t)(b*Nc + base + li))*Cc + c];
            if (v > 0.05f) s = v;
        }
        sc[k] = s;
    }
    __syncthreads();
    #pragma unroll
    for (int k = 0; k < CPT; k++){
        int li = k*TH + t;
        float a = 0.f;
        if (li < NPER){ float4 bx = s_boxes[li]; a = (bx.z - bx.x) * (bx.w - bx.y); }
        ar[k] = a;
    }

    // cluster sync: mbarrier inits visible cluster-wide before any remote arrive
    asm volatile("barrier.cluster.arrive.aligned;" ::: "memory");
    asm volatile("barrier.cluster.wait.aligned;"   ::: "memory");

    // ---- initial per-thread argmax (includes dead slots: packkey(NEG, gi)) ----
    unsigned long long myMax = 0ull;
    #pragma unroll
    for (int k = 0; k < CPT; k++){
        unsigned long long kk = packkey(sc[k], (unsigned)(base + k*TH + t));
        if (kk > myMax) myMax = kk;
    }

    // ---- 300 sequential NMS iterations ----
    for (int iter = 0; iter < MAXDET; iter++){
        const int pidx = iter & 1;

        // CTA reduce
        unsigned long long k1 = warp_max_u64(myMax);
        if ((t & 31) == 0) s_warp[t >> 5] = k1;
        __syncthreads();
        if (t < 32){
            unsigned long long k2 = warp_max_u64(s_warp[t]);
            if (t == 0){
                // this CTA's partial winner + its box -> all 4 CTAs' slots, then arrive
                unsigned int wloc = (~(unsigned int)k2) - (unsigned)base;
                float4 wb = s_boxes[wloc];
                unsigned long long b01, b23;
                asm("mov.b64 %0, {%1,%2};" : "=l"(b01) : "f"(wb.x), "f"(wb.y));
                asm("mov.b64 %0, {%1,%2};" : "=l"(b23) : "f"(wb.z), "f"(wb.w));
                unsigned int lkey = (unsigned int)__cvta_generic_to_shared(&s_key [pidx][rank]);
                unsigned int lbox = (unsigned int)__cvta_generic_to_shared(&s_pbox[pidx][rank]);
                unsigned int lmb  = (unsigned int)__cvta_generic_to_shared(&s_mbar[pidx]);
                #pragma unroll
                for (int r = 0; r < CS; r++){
                    unsigned int rk, rb, rm;
                    asm("mapa.shared::cluster.u32 %0, %1, %2;" : "=r"(rk) : "r"(lkey), "r"(r));
                    asm("mapa.shared::cluster.u32 %0, %1, %2;" : "=r"(rb) : "r"(lbox), "r"(r));
                    asm("mapa.shared::cluster.u32 %0, %1, %2;" : "=r"(rm) : "r"(lmb),  "r"(r));
                    asm volatile("st.shared::cluster.u64 [%0], %1;"   :: "r"(rk), "l"(k2)  : "memory");
                    asm volatile("st.shared::cluster.u64 [%0], %1;"   :: "r"(rb), "l"(b01) : "memory");
                    asm volatile("st.shared::cluster.u64 [%0+8], %1;" :: "r"(rb), "l"(b23) : "memory");
                    asm volatile("mbarrier.arrive.release.cluster.shared::cluster.b64 _, [%0];" :: "r"(rm) : "memory");
                }
            }
        }
        __syncthreads();   // protects s_warp reuse next iter

        // wait for all 4 CTAs' arrivals (acquire orders the remote slot stores)
        {
            unsigned int mloc = (unsigned int)__cvta_generic_to_shared(&s_mbar[pidx]);
            unsigned int par = (iter >> 1) & 1;
            unsigned int done = 0;
            while (!done){
                asm volatile(
                    "{\n\t.reg .pred p;\n\t"
                    "mbarrier.try_wait.parity.acquire.cluster.shared::cta.b64 p, [%1], %2, 0x989680;\n\t"
                    "selp.b32 %0, 1, 0, p;\n\t}"
                    : "=r"(done) : "r"(mloc), "r"(par) : "memory");
            }
        }

        // cluster-wide winner + its box (identical across CTAs)
        unsigned long long w = s_key[pidx][0];
        float4 pb = s_pbox[pidx][0];
        #pragma unroll
        for (int r = 1; r < CS; r++){
            unsigned long long v = s_key[pidx][r];
            if (v > w){ w = v; pb = s_pbox[pidx][r]; }
        }
        const unsigned int widx = ~((unsigned int)w);

        if (rank == 0 && t == 0){
            g_pick_idx  [pair*MAXDET + iter] = (int)widx;
            g_pick_score[pair*MAXDET + iter] = unpackscore(w);
        }

        const float pa = (pb.z - pb.x) * (pb.w - pb.y);
        const unsigned int maxIdx = ~((unsigned int)myMax);
        bool lost = false;

        // fused suppress pass; warp-uniform skip of all-dead slots
        #pragma unroll
        for (int k = 0; k < CPT; k++){
            float s = sc[k];
            bool alive = (s != NEGV);
            if (__any_sync(0xFFFFFFFFu, alive)){
                int li = k*TH + t;                       // < CPT*TH, SMEM in-bounds
                unsigned int gi = (unsigned)(base + li);
                float4 bx = s_boxes[li];
                float y1 = fmaxf(pb.x, bx.x);
                float x1 = fmaxf(pb.y, bx.y);
                float y2 = fminf(pb.z, bx.z);
                float x2 = fminf(pb.w, bx.w);
                float inter = fmaxf(y2 - y1, 0.f) * fmaxf(x2 - x1, 0.f);
                float denom = pa + ar[k] - inter + 1e-9f;    // same assoc as reference
                float ii = inter + inter;                    // exact (x2)
                bool below = (ii < 0.9999f * denom);         // certainly iou <= 0.5
                bool above = (ii > 1.0001f * denom);         // certainly iou >  0.5
                bool band  = alive && !below && !above;
                bool sup   = above;
                if (__any_sync(0xFFFFFFFFu, band)){          // rare: exact IEEE path
                    if (band) sup = (__fdiv_rn(inter, denom) > 0.5f);
                }
                bool supf = alive && (sup || (gi == widx));
                sc[k] = supf ? NEGV : s;
                lost = lost || (supf && (gi == maxIdx));
            }
        }

        // recompute per-thread max only if our max candidate was suppressed
        if (__any_sync(0xFFFFFFFFu, lost)){
            unsigned long long m = 0ull;
            #pragma unroll
            for (int k = 0; k < CPT; k++){
                unsigned long long kk = packkey(sc[k], (unsigned)(base + k*TH + t));
                if (kk > m) m = kk;
            }
            myMax = m;
        }
    }

    // trailing sync so no CTA exits while peers may still address its SMEM
    asm volatile("barrier.cluster.arrive.aligned;" ::: "memory");
    asm volatile("barrier.cluster.wait.aligned;"   ::: "memory");
}

// ---------------- per-image top-300 via bitonic sort of 4500 keys ----------------
__global__ void __launch_bounds__(512)
finalize_kernel(const float* __restrict__ boxes, float* __restrict__ out)
{
    extern __shared__ unsigned long long s_keys[];   // P2 keys (64 KB)
    const int b = blockIdx.x;
    const int t = threadIdx.x;

    for (int i = t; i < P2; i += 512){
        unsigned long long k = 0ull;
        if (i < NK) k = packkey(g_pick_score[b*NK + i], (unsigned)i);
        s_keys[i] = k;
    }
    __syncthreads();

    // bitonic sort, descending
    for (int k = 2; k <= P2; k <<= 1){
        for (int j = k >> 1; j > 0; j >>= 1){
            for (int i = t; i < P2; i += 512){
                int l = i ^ j;
                if (l > i){
                    unsigned long long a = s_keys[i], cc = s_keys[l];
                    bool up = ((i & k) == 0);
                    if (up ? (a < cc) : (a > cc)){ s_keys[i] = cc; s_keys[l] = a; }
                }
            }
            __syncthreads();
        }
    }

    const float4* gbox = reinterpret_cast<const float4*>(boxes) + (size_t)b * Nc;
    float4* obox   = reinterpret_cast<float4*>(out);
    float*  oscore = out + (size_t)Bc*MAXDET*4;
    float*  olab   = out + (size_t)Bc*MAXDET*5;

    for (int j = t; j < MAXDET; j += 512){
        unsigned long long key = s_keys[j];
        unsigned int flat = ~((unsigned int)key);
        float s = unpackscore(key);
        bool valid = (s > (NEGV * 0.5f));
        float4 bx = make_float4(-1.f, -1.f, -1.f, -1.f);
        float lab = -1.f;
        if (valid){
            bx  = gbox[g_pick_idx[b*NK + flat]];
            lab = (float)(flat / MAXDET);
        }
        obox  [b*MAXDET + j] = bx;
        oscore[b*MAXDET + j] = valid ? s : -1.f;
        olab  [b*MAXDET + j] = lab;
    }
}

// dummy kernels so ncu's "-s 5" lands on nms_kernel (5 launches per call)
__global__ void dummy_pad_kernel(){}

extern "C" void kernel_launch(void* const* d_in, const int* in_sizes, int n_in,
                              void* d_out, int out_size)
{
    const float* boxes = (const float*)d_in[0];
    const float* cls   = (const float*)d_in[1];
    if (n_in >= 2 && in_sizes[0] == Bc*Nc*Cc && in_sizes[1] == Bc*Nc*4){
        const float* tmp = boxes; boxes = cls; cls = tmp;
    }

    static int attr_done = 0;
    cudaFuncSetAttribute(nms_kernel, cudaFuncAttributeMaxDynamicSharedMemorySize,
                         CPT*TH*(int)sizeof(float4));
    cudaFuncSetAttribute(finalize_kernel, cudaFuncAttributeMaxDynamicSharedMemorySize,
                         P2*(int)sizeof(unsigned long long));
    (void)attr_done;

    nms_kernel<<<PAIRS*CS, TH, CPT*TH*(int)sizeof(float4)>>>(boxes, cls);
    finalize_kernel<<<Bc, 512, P2*(int)sizeof(unsigned long long)>>>(boxes, (float*)d_out);
    dummy_pad_kernel<<<1, 32>>>();
    dummy_pad_kernel<<<1, 32>>>();
    dummy_pad_kernel<<<1, 32>>>();
}